// round 14
// baseline (speedup 1.0000x reference)
#include <cuda_runtime.h>
#include <cuda_fp16.h>
#include <math.h>
#include <stdint.h>

#define TT     512
#define HH     64
#define DD     576
#define DV     512
#define NKV    8192
#define TOPK   1024
#define TILE   32
#define NTILES 32
#define HB     32
#define KSTRIDE 584               // halves per KV/Q smem row (1168 B)
#define ROWB   (KSTRIDE * 2)      // 1168 bytes
#define CPROW  1152               // bytes copied per KV row
#define PSTRIDE 40
#define KVBUF  (TILE * KSTRIDE)
#define SCALE_F (1.0f / 24.0f)
#define TILE_TX (TILE * CPROW)

// smem: sKV 3 bufs | sP | sPart | sLp | sIdx[3][32] | mbar[3]
#define SP_OFFB    (3 * KVBUF * 2)
#define SPART_OFFB (SP_OFFB + HB * PSTRIDE * 2)
#define SLP_OFFB   (SPART_OFFB + 8 * 4 * 32 * 4 * 4)
#define SIDX_OFFB  (SLP_OFFB + 4 * 32 * 4)
#define SMB_OFFB   (SIDX_OFFB + 3 * 32 * 4)
#define SMEM_BYTES (SMB_OFFB + 64)

__device__ __align__(16) half g_kvh[(size_t)NKV * DD];

__global__ void __launch_bounds__(256)
kv_to_half_kernel(const float* __restrict__ kv)
{
    size_t i = (size_t)blockIdx.x * 256 + threadIdx.x;
    float4 v = ((const float4*)kv)[i];
    half2 a = __floats2half2_rn(v.x, v.y);
    half2 b = __floats2half2_rn(v.z, v.w);
    uint2 u; u.x = *(uint32_t*)&a; u.y = *(uint32_t*)&b;
    ((uint2*)g_kvh)[i] = u;
}

__device__ __forceinline__ void ldsm_x4(uint32_t& r0, uint32_t& r1, uint32_t& r2, uint32_t& r3, uint32_t a) {
    asm volatile("ldmatrix.sync.aligned.m8n8.x4.shared.b16 {%0,%1,%2,%3}, [%4];"
                 : "=r"(r0), "=r"(r1), "=r"(r2), "=r"(r3) : "r"(a));
}
__device__ __forceinline__ void ldsm_x4t(uint32_t& r0, uint32_t& r1, uint32_t& r2, uint32_t& r3, uint32_t a) {
    asm volatile("ldmatrix.sync.aligned.m8n8.x4.trans.shared.b16 {%0,%1,%2,%3}, [%4];"
                 : "=r"(r0), "=r"(r1), "=r"(r2), "=r"(r3) : "r"(a));
}
__device__ __forceinline__ void mma16816(float& d0, float& d1, float& d2, float& d3,
                                         uint32_t a0, uint32_t a1, uint32_t a2, uint32_t a3,
                                         uint32_t b0, uint32_t b1,
                                         float c0, float c1, float c2, float c3) {
    asm volatile("mma.sync.aligned.m16n8k16.row.col.f32.f16.f16.f32 "
                 "{%0,%1,%2,%3},{%4,%5,%6,%7},{%8,%9},{%10,%11,%12,%13};"
                 : "=f"(d0), "=f"(d1), "=f"(d2), "=f"(d3)
                 : "r"(a0), "r"(a1), "r"(a2), "r"(a3), "r"(b0), "r"(b1),
                   "f"(c0), "f"(c1), "f"(c2), "f"(c3));
}
#define MB_WAIT(mb, ph) do { \
    asm volatile("{\n .reg .pred P1;\n WL%=:\n" \
        " mbarrier.try_wait.parity.acquire.cta.shared::cta.b64 P1, [%0], %1, 0x989680;\n" \
        " @P1 bra.uni WD%=;\n bra.uni WL%=;\n WD%=:\n}" :: "r"(mb), "r"(ph) : "memory"); \
} while (0)

__global__ void __launch_bounds__(256, 1)
mla_v10_kernel(const float* __restrict__ q,     // [T,H,D]
               const int*   __restrict__ topk,  // [T,TOPK]
               const float* __restrict__ sink,  // [H]
               float*       __restrict__ out)   // [T,H,DV]
{
    extern __shared__ char smem_raw[];
    half*  sKVh  = (half*)smem_raw;                       // [3][KVBUF]
    half*  sP    = (half*)(smem_raw + SP_OFFB);           // [32][40]
    float* sPart = (float*)(smem_raw + SPART_OFFB);       // [8 dst][4 src][32][4]
    float* sLp   = (float*)(smem_raw + SLP_OFFB);         // [4][32]
    int*   sIdx  = (int*)(smem_raw + SIDX_OFFB);          // [3][32]

    const int hblk = blockIdx.x;
    const int tok  = blockIdx.y;
    const int tid  = threadIdx.x;
    const int lt   = tid & 31;
    const int w    = tid >> 5;
    const int wrb  = w >> 2;           // head rowblock: 16 heads
    const int ks   = w & 3;            // k-split quarter (144 dims) + owns token n-tile ks

    const uint32_t skv0 = (uint32_t)__cvta_generic_to_shared(sKVh);
    const uint32_t spb  = (uint32_t)__cvta_generic_to_shared(sP);
    const uint32_t mbar = skv0 + SMB_OFFB;                // 3 mbarriers

    if (tid < 3) {
        asm volatile("mbarrier.init.shared.b64 [%0], 1;" :: "r"(mbar + tid * 8) : "memory");
    }

    // ---- stage Q (pre-scaled) into sKV buf0 — coalesced ----
    {
        int h = tid >> 3, j = tid & 7;
        const float4* qs = (const float4*)(q + ((size_t)tok * HH + hblk * HB + h) * DD) + j;
        half* qd = sKVh + h * KSTRIDE;
        #pragma unroll
        for (int i = 0; i < 18; ++i) {
            float4 v = qs[i * 8];
            half2 h0 = __floats2half2_rn(v.x * SCALE_F, v.y * SCALE_F);
            half2 h1 = __floats2half2_rn(v.z * SCALE_F, v.w * SCALE_F);
            uint2 u; u.x = *(uint32_t*)&h0; u.y = *(uint32_t*)&h1;
            *(uint2*)(qd + j * 4 + i * 32) = u;
        }
    }
    __syncthreads();

    // Q A-fragments for this warp's 144-dim slice: 9 k-steps
    uint32_t qf[36];
    {
        uint32_t qa = skv0 + (uint32_t)(((wrb * 16 + (lt & 15)) * KSTRIDE + ks * 144 + (lt >> 4) * 8) * 2);
        #pragma unroll
        for (int s = 0; s < 9; ++s) {
            ldsm_x4(qf[4*s], qf[4*s+1], qf[4*s+2], qf[4*s+3], qa);
            qa += 32;
        }
    }
    __syncthreads();   // Q frags read before gather overwrites buf0

    const int* tkp = topk + (size_t)tok * TOPK;

    // ---- bulk gather: warp 0, one row per lane, into buf tile%3 ----
    auto gather = [&](int tile) {
        int buf = tile % 3;
        int raw = tkp[tile * TILE + lt];
        sIdx[buf * 32 + lt] = raw;
        int r2 = raw < 0 ? 0 : raw;
        if (lt == 0) {
            asm volatile("mbarrier.arrive.expect_tx.shared.b64 _, [%0], %1;"
                         :: "r"(mbar + buf * 8), "r"((uint32_t)TILE_TX) : "memory");
        }
        __syncwarp();
        uint32_t dst = skv0 + (uint32_t)(buf * (KVBUF * 2) + lt * ROWB);
        const half* src = g_kvh + (size_t)r2 * DD;
        asm volatile("cp.async.bulk.shared::cta.global.mbarrier::complete_tx::bytes [%0], [%1], %2, [%3];"
                     :: "r"(dst), "l"(src), "r"((uint32_t)CPROW), "r"(mbar + buf * 8) : "memory");
    };

    // prologue: issue gather(0)
    if (w == 0) gather(0);

    float accO[2][8][4];
    #pragma unroll
    for (int m = 0; m < 2; ++m)
        #pragma unroll
        for (int n = 0; n < 8; ++n)
            accO[m][n][0] = accO[m][n][1] = accO[m][n][2] = accO[m][n][3] = 0.0f;

    float rs0 = 0.0f, rs1 = 0.0f;

    const uint32_t qkB_off = (uint32_t)(((lt & 15) * KSTRIDE + ks * 144 + (lt >> 4) * 8) * 2);
    const uint32_t pvB_off = (uint32_t)((lt * KSTRIDE + w * 64) * 2);
    const int rowa = wrb * 16 + (lt >> 2);

    for (int kt = 0; kt < NTILES; ++kt) {
        const int cur = kt % 3;
        const uint32_t kvb = skv0 + (uint32_t)(cur * (KVBUF * 2));

        // issue gather(kt+1): writes buf (kt+1)%3; last reader was PV(kt-2), done for
        // all warps (everyone is past B2(kt-1)). Full tile of hiding before its use.
        if (kt + 1 < NTILES && w == 0) gather(kt + 1);

        // KV(kt) ready? (issued one full tile ago)
        MB_WAIT(mbar + cur * 8, (kt / 3) & 1);

        // ---- QK: warp tile [16h x 32t] over 144 dims (9 k-steps), A in registers ----
        float c[4][4];
        #pragma unroll
        for (int j = 0; j < 4; ++j) c[j][0] = c[j][1] = c[j][2] = c[j][3] = 0.0f;
        {
            uint32_t ka0 = kvb + qkB_off;
            uint32_t ka1 = ka0 + (uint32_t)(16 * KSTRIDE * 2);
            #pragma unroll
            for (int s = 0; s < 9; ++s) {
                uint32_t b0, b1, b2, b3;
                ldsm_x4(b0, b1, b2, b3, ka0); ka0 += 32;
                mma16816(c[0][0], c[0][1], c[0][2], c[0][3],
                         qf[4*s], qf[4*s+1], qf[4*s+2], qf[4*s+3], b0, b2,
                         c[0][0], c[0][1], c[0][2], c[0][3]);
                mma16816(c[1][0], c[1][1], c[1][2], c[1][3],
                         qf[4*s], qf[4*s+1], qf[4*s+2], qf[4*s+3], b1, b3,
                         c[1][0], c[1][1], c[1][2], c[1][3]);
                uint32_t e0, e1, e2, e3;
                ldsm_x4(e0, e1, e2, e3, ka1); ka1 += 32;
                mma16816(c[2][0], c[2][1], c[2][2], c[2][3],
                         qf[4*s], qf[4*s+1], qf[4*s+2], qf[4*s+3], e0, e2,
                         c[2][0], c[2][1], c[2][2], c[2][3]);
                mma16816(c[3][0], c[3][1], c[3][2], c[3][3],
                         qf[4*s], qf[4*s+1], qf[4*s+2], qf[4*s+3], e1, e3,
                         c[3][0], c[3][1], c[3][2], c[3][3]);
            }
        }

        // export the 3 token n-tiles owned by partner warps (same wrb)
        #pragma unroll
        for (int j = 0; j < 4; ++j) {
            if (j != ks) {
                float* pb = sPart + (((wrb * 4 + j) * 4 + ks) * 32 + lt) * 4;
                *(float4*)pb = make_float4(c[j][0], c[j][1], c[j][2], c[j][3]);
            }
        }
        __syncthreads();   // B1: partials visible; all PV(kt-1) complete

        // ---- softmax (fixed base 0) on own n-tile ----
        {
            float s0 = c[ks][0], s1 = c[ks][1], s2 = c[ks][2], s3 = c[ks][3];
            #pragma unroll
            for (int src = 0; src < 4; ++src) {
                if (src != ks) {
                    float4 pp = *(const float4*)(sPart + ((w * 4 + src) * 32 + lt) * 4);
                    s0 += pp.x; s1 += pp.y; s2 += pp.z; s3 += pp.w;
                }
            }
            int t0 = ks * 8 + (lt & 3) * 2;
            int i0 = sIdx[cur * 32 + t0];
            int i1 = sIdx[cur * 32 + t0 + 1];
            float p0 = (i0 < 0) ? 0.f : __expf(s0);
            float p1 = (i1 < 0) ? 0.f : __expf(s1);
            float p2 = (i0 < 0) ? 0.f : __expf(s2);
            float p3 = (i1 < 0) ? 0.f : __expf(s3);
            rs0 += p0 + p1;
            rs1 += p2 + p3;
            *(half2*)(sP + rowa * PSTRIDE + t0)       = __floats2half2_rn(p0, p1);
            *(half2*)(sP + (rowa + 8) * PSTRIDE + t0) = __floats2half2_rn(p2, p3);
        }
        __syncthreads();   // B2: P visible

        // ---- PV: warp tile [32h x 64d] = P[32x32] @ V[32x64] ----
        // (no trailing barrier: sP/sPart rewrites are ordered by B1/B2 of kt+1,
        //  and KV-buffer reuse is ordered by the 3-buffer rotation)
        {
            uint32_t ap[2][2][4];
            #pragma unroll
            for (int mi = 0; mi < 2; ++mi)
                #pragma unroll
                for (int k2 = 0; k2 < 2; ++k2) {
                    uint32_t aa = spb + (uint32_t)(((mi * 16 + (lt & 15)) * PSTRIDE + k2 * 16 + (lt >> 4) * 8) * 2);
                    ldsm_x4(ap[mi][k2][0], ap[mi][k2][1], ap[mi][k2][2], ap[mi][k2][3], aa);
                }
            uint32_t bbase = kvb + pvB_off;
            #pragma unroll
            for (int n2 = 0; n2 < 8; ++n2) {
                uint32_t b0, b1, b2, b3;
                ldsm_x4t(b0, b1, b2, b3, bbase + (uint32_t)(n2 * 16));
                #pragma unroll
                for (int mi = 0; mi < 2; ++mi)
                    mma16816(accO[mi][n2][0], accO[mi][n2][1], accO[mi][n2][2], accO[mi][n2][3],
                             ap[mi][0][0], ap[mi][0][1], ap[mi][0][2], ap[mi][0][3], b0, b1,
                             accO[mi][n2][0], accO[mi][n2][1], accO[mi][n2][2], accO[mi][n2][3]);
                #pragma unroll
                for (int mi = 0; mi < 2; ++mi)
                    mma16816(accO[mi][n2][0], accO[mi][n2][1], accO[mi][n2][2], accO[mi][n2][3],
                             ap[mi][1][0], ap[mi][1][1], ap[mi][1][2], ap[mi][1][3], b2, b3,
                             accO[mi][n2][0], accO[mi][n2][1], accO[mi][n2][2], accO[mi][n2][3]);
            }
        }
    }

    // ---- epilogue ----
    __syncthreads();
    {
        rs0 += __shfl_xor_sync(0xffffffffu, rs0, 1);
        rs0 += __shfl_xor_sync(0xffffffffu, rs0, 2);
        rs1 += __shfl_xor_sync(0xffffffffu, rs1, 1);
        rs1 += __shfl_xor_sync(0xffffffffu, rs1, 2);
        if ((lt & 3) == 0) {
            sLp[ks * 32 + rowa]     = rs0;
            sLp[ks * 32 + rowa + 8] = rs1;
        }
    }
    __syncthreads();

    {
        float* ob = out + ((size_t)tok * HH + hblk * HB) * DV;
        #pragma unroll
        for (int mi = 0; mi < 2; ++mi) {
            int r0 = mi * 16 + (lt >> 2);
            int r1 = r0 + 8;
            float d0 = sLp[r0] + sLp[32 + r0] + sLp[64 + r0] + sLp[96 + r0]
                     + __expf(sink[hblk * HB + r0]);
            float d1 = sLp[r1] + sLp[32 + r1] + sLp[64 + r1] + sLp[96 + r1]
                     + __expf(sink[hblk * HB + r1]);
            float rc0 = 1.0f / d0;
            float rc1 = 1.0f / d1;
            #pragma unroll
            for (int n2 = 0; n2 < 8; ++n2) {
                int d = w * 64 + n2 * 8 + (lt & 3) * 2;
                *(float2*)(ob + (size_t)r0 * DV + d) =
                    make_float2(accO[mi][n2][0] * rc0, accO[mi][n2][1] * rc0);
                *(float2*)(ob + (size_t)r1 * DV + d) =
                    make_float2(accO[mi][n2][2] * rc1, accO[mi][n2][3] * rc1);
            }
        }
    }
}

extern "C" void kernel_launch(void* const* d_in, const int* in_sizes, int n_in,
                              void* d_out, int out_size)
{
    const float* q    = (const float*)d_in[0];
    const float* kv   = (const float*)d_in[1];
    const int*   topk = (const int*)d_in[2];
    const float* sink = (const float*)d_in[3];
    float*       out  = (float*)d_out;

    kv_to_half_kernel<<<(NKV * DD / 4) / 256, 256>>>(kv);

    cudaFuncSetAttribute(mla_v10_kernel,
                         cudaFuncAttributeMaxDynamicSharedMemorySize, SMEM_BYTES);

    dim3 grid(HH / HB, TT);   // (2, 512)
    dim3 block(256);
    mla_v10_kernel<<<grid, block, SMEM_BYTES>>>(q, topk, sink, out);
}

// round 15
// speedup vs baseline: 1.3989x; 1.3989x over previous
#include <cuda_runtime.h>
#include <cuda_fp16.h>
#include <math.h>
#include <stdint.h>

#define TT     512
#define HH     64
#define DD     576
#define DV     512
#define NKV    8192
#define TOPK   1024
#define TILE   32
#define NTILES 32
#define HB     32
#define KSTRIDE 584               // halves per KV/Q smem row (1168 B)
#define ROWB   (KSTRIDE * 2)      // 1168 bytes
#define CPROW  1152               // bytes copied per KV row
#define PSTRIDE 40
#define KVBUF  (TILE * KSTRIDE)
#define SCALE_F (1.0f / 24.0f)
#define TILE_TX (TILE * CPROW)

#define SP_OFFB    (2 * KVBUF * 2)
#define SPART_OFFB (SP_OFFB + HB * PSTRIDE * 2)
#define SLP_OFFB   (SPART_OFFB + 8 * 4 * 32 * 4 * 4)
#define SIDX_OFFB  (SLP_OFFB + 4 * 32 * 4)
#define SMB_OFFB   (SIDX_OFFB + 2 * 32 * 4)
#define SMEM_BYTES (SMB_OFFB + 64)

__device__ __align__(16) half g_kvh[(size_t)NKV * DD];

__global__ void __launch_bounds__(256)
kv_to_half_kernel(const float* __restrict__ kv)
{
    size_t i = (size_t)blockIdx.x * 256 + threadIdx.x;
    float4 v = ((const float4*)kv)[i];
    half2 a = __floats2half2_rn(v.x, v.y);
    half2 b = __floats2half2_rn(v.z, v.w);
    uint2 u; u.x = *(uint32_t*)&a; u.y = *(uint32_t*)&b;
    ((uint2*)g_kvh)[i] = u;
}

__device__ __forceinline__ void ldsm_x4(uint32_t& r0, uint32_t& r1, uint32_t& r2, uint32_t& r3, uint32_t a) {
    asm volatile("ldmatrix.sync.aligned.m8n8.x4.shared.b16 {%0,%1,%2,%3}, [%4];"
                 : "=r"(r0), "=r"(r1), "=r"(r2), "=r"(r3) : "r"(a));
}
__device__ __forceinline__ void ldsm_x4t(uint32_t& r0, uint32_t& r1, uint32_t& r2, uint32_t& r3, uint32_t a) {
    asm volatile("ldmatrix.sync.aligned.m8n8.x4.trans.shared.b16 {%0,%1,%2,%3}, [%4];"
                 : "=r"(r0), "=r"(r1), "=r"(r2), "=r"(r3) : "r"(a));
}
__device__ __forceinline__ void mma16816(float& d0, float& d1, float& d2, float& d3,
                                         uint32_t a0, uint32_t a1, uint32_t a2, uint32_t a3,
                                         uint32_t b0, uint32_t b1,
                                         float c0, float c1, float c2, float c3) {
    asm volatile("mma.sync.aligned.m16n8k16.row.col.f32.f16.f16.f32 "
                 "{%0,%1,%2,%3},{%4,%5,%6,%7},{%8,%9},{%10,%11,%12,%13};"
                 : "=f"(d0), "=f"(d1), "=f"(d2), "=f"(d3)
                 : "r"(a0), "r"(a1), "r"(a2), "r"(a3), "r"(b0), "r"(b1),
                   "f"(c0), "f"(c1), "f"(c2), "f"(c3));
}
#define MB_WAIT(mb, ph) do { \
    asm volatile("{\n .reg .pred P1;\n WL%=:\n" \
        " mbarrier.try_wait.parity.acquire.cta.shared::cta.b64 P1, [%0], %1, 0x989680;\n" \
        " @P1 bra.uni WD%=;\n bra.uni WL%=;\n WD%=:\n}" :: "r"(mb), "r"(ph) : "memory"); \
} while (0)

__global__ void __launch_bounds__(256, 2)
mla_v11_kernel(const float* __restrict__ q,     // [T,H,D]
               const int*   __restrict__ topk,  // [T,TOPK]
               const float* __restrict__ sink,  // [H]
               float*       __restrict__ out)   // [T,H,DV]
{
    extern __shared__ char smem_raw[];
    half*  sKVh  = (half*)smem_raw;                       // [2][KVBUF]
    half*  sP    = (half*)(smem_raw + SP_OFFB);           // [32][40]
    float* sPart = (float*)(smem_raw + SPART_OFFB);       // [8 dst][4 src][32][4]
    float* sLp   = (float*)(smem_raw + SLP_OFFB);         // [4][32]
    int*   sIdx  = (int*)(smem_raw + SIDX_OFFB);          // [2][32]

    const int hblk = blockIdx.x;
    const int tok  = blockIdx.y;
    const int tid  = threadIdx.x;
    const int lt   = tid & 31;
    const int w    = tid >> 5;
    const int wrb  = w >> 2;           // head rowblock: 16 heads
    const int ks   = w & 3;            // k-split quarter (144 dims) + owns token n-tile ks

    const uint32_t skv0 = (uint32_t)__cvta_generic_to_shared(sKVh);
    const uint32_t spb  = (uint32_t)__cvta_generic_to_shared(sP);
    const uint32_t mbar = skv0 + SMB_OFFB;

    if (tid < 2) {
        asm volatile("mbarrier.init.shared.b64 [%0], 1;" :: "r"(mbar + tid * 8) : "memory");
    }

    // ---- stage Q (pre-scaled) into sKV buf0 — coalesced ----
    {
        int h = tid >> 3, j = tid & 7;
        const float4* qs = (const float4*)(q + ((size_t)tok * HH + hblk * HB + h) * DD) + j;
        half* qd = sKVh + h * KSTRIDE;
        #pragma unroll
        for (int i = 0; i < 18; ++i) {
            float4 v = qs[i * 8];
            half2 h0 = __floats2half2_rn(v.x * SCALE_F, v.y * SCALE_F);
            half2 h1 = __floats2half2_rn(v.z * SCALE_F, v.w * SCALE_F);
            uint2 u; u.x = *(uint32_t*)&h0; u.y = *(uint32_t*)&h1;
            *(uint2*)(qd + j * 4 + i * 32) = u;
        }
    }
    __syncthreads();

    // Q A-fragments for this warp's 144-dim slice: 9 k-steps
    uint32_t qf[36];
    {
        uint32_t qa = skv0 + (uint32_t)(((wrb * 16 + (lt & 15)) * KSTRIDE + ks * 144 + (lt >> 4) * 8) * 2);
        #pragma unroll
        for (int s = 0; s < 9; ++s) {
            ldsm_x4(qf[4*s], qf[4*s+1], qf[4*s+2], qf[4*s+3], qa);
            qa += 32;
        }
    }
    __syncthreads();   // Q frags read before gather overwrites buf0

    const int* tkp = topk + (size_t)tok * TOPK;

    // ---- bulk gather: warp 0, one row per lane ----
    auto gather = [&](int tile) {
        int buf = tile & 1;
        int raw = tkp[tile * TILE + lt];
        sIdx[buf * 32 + lt] = raw;
        int r2 = raw < 0 ? 0 : raw;
        if (lt == 0) {
            asm volatile("mbarrier.arrive.expect_tx.shared.b64 _, [%0], %1;"
                         :: "r"(mbar + buf * 8), "r"((uint32_t)TILE_TX) : "memory");
        }
        __syncwarp();
        uint32_t dst = skv0 + (uint32_t)(buf * (KVBUF * 2) + lt * ROWB);
        const half* src = g_kvh + (size_t)r2 * DD;
        asm volatile("cp.async.bulk.shared::cta.global.mbarrier::complete_tx::bytes [%0], [%1], %2, [%3];"
                     :: "r"(dst), "l"(src), "r"((uint32_t)CPROW), "r"(mbar + buf * 8) : "memory");
    };

    // prologue: gather tile 0, wait, sync
    if (w == 0) gather(0);
    MB_WAIT(mbar, 0);
    __syncthreads();

    float accO[2][8][4];
    #pragma unroll
    for (int m = 0; m < 2; ++m)
        #pragma unroll
        for (int n = 0; n < 8; ++n)
            accO[m][n][0] = accO[m][n][1] = accO[m][n][2] = accO[m][n][3] = 0.0f;

    float rs0 = 0.0f, rs1 = 0.0f;

    const uint32_t qkB_off = (uint32_t)(((lt & 15) * KSTRIDE + ks * 144 + (lt >> 4) * 8) * 2);
    const uint32_t pvB_off = (uint32_t)((lt * KSTRIDE + w * 64) * 2);
    const int rowa = wrb * 16 + (lt >> 2);

    for (int kt = 0; kt < NTILES; ++kt) {
        const int cur = kt & 1;
        const uint32_t kvb = skv0 + (uint32_t)(cur * (KVBUF * 2));
        const bool hasNext = (kt + 1 < NTILES);

        // ---- issue next-tile bulk gather (warp 0; hides under whole tile body) ----
        if (hasNext && w == 0) gather(kt + 1);

        // ---- QK: warp tile [16h x 32t] over 144 dims (9 k-steps), A in registers ----
        float c[4][4];
        #pragma unroll
        for (int j = 0; j < 4; ++j) c[j][0] = c[j][1] = c[j][2] = c[j][3] = 0.0f;
        {
            uint32_t ka0 = kvb + qkB_off;
            uint32_t ka1 = ka0 + (uint32_t)(16 * KSTRIDE * 2);
            #pragma unroll
            for (int s = 0; s < 9; ++s) {
                uint32_t b0, b1, b2, b3;
                ldsm_x4(b0, b1, b2, b3, ka0); ka0 += 32;
                mma16816(c[0][0], c[0][1], c[0][2], c[0][3],
                         qf[4*s], qf[4*s+1], qf[4*s+2], qf[4*s+3], b0, b2,
                         c[0][0], c[0][1], c[0][2], c[0][3]);
                mma16816(c[1][0], c[1][1], c[1][2], c[1][3],
                         qf[4*s], qf[4*s+1], qf[4*s+2], qf[4*s+3], b1, b3,
                         c[1][0], c[1][1], c[1][2], c[1][3]);
                uint32_t e0, e1, e2, e3;
                ldsm_x4(e0, e1, e2, e3, ka1); ka1 += 32;
                mma16816(c[2][0], c[2][1], c[2][2], c[2][3],
                         qf[4*s], qf[4*s+1], qf[4*s+2], qf[4*s+3], e0, e2,
                         c[2][0], c[2][1], c[2][2], c[2][3]);
                mma16816(c[3][0], c[3][1], c[3][2], c[3][3],
                         qf[4*s], qf[4*s+1], qf[4*s+2], qf[4*s+3], e1, e3,
                         c[3][0], c[3][1], c[3][2], c[3][3]);
            }
        }

        // export the 3 token n-tiles owned by partner warps (SAME wrb group)
        #pragma unroll
        for (int j = 0; j < 4; ++j) {
            if (j != ks) {
                float* pb = sPart + (((wrb * 4 + j) * 4 + ks) * 32 + lt) * 4;
                *(float4*)pb = make_float4(c[j][0], c[j][1], c[j][2], c[j][3]);
            }
        }
        // B1 (named, per wrb group of 4 warps): exchange is wrb-local;
        // sIdx visibility across groups is ordered by B3 of the previous tile.
        asm volatile("bar.sync %0, 128;" :: "r"(1 + wrb) : "memory");

        // ---- softmax (fixed base 0) on own n-tile ----
        {
            float s0 = c[ks][0], s1 = c[ks][1], s2 = c[ks][2], s3 = c[ks][3];
            #pragma unroll
            for (int src = 0; src < 4; ++src) {
                if (src != ks) {
                    float4 pp = *(const float4*)(sPart + ((w * 4 + src) * 32 + lt) * 4);
                    s0 += pp.x; s1 += pp.y; s2 += pp.z; s3 += pp.w;
                }
            }
            int t0 = ks * 8 + (lt & 3) * 2;
            int i0 = sIdx[cur * 32 + t0];
            int i1 = sIdx[cur * 32 + t0 + 1];
            float p0 = (i0 < 0) ? 0.f : __expf(s0);
            float p1 = (i1 < 0) ? 0.f : __expf(s1);
            float p2 = (i0 < 0) ? 0.f : __expf(s2);
            float p3 = (i1 < 0) ? 0.f : __expf(s3);
            rs0 += p0 + p1;
            rs1 += p2 + p3;
            *(half2*)(sP + rowa * PSTRIDE + t0)       = __floats2half2_rn(p0, p1);
            *(half2*)(sP + (rowa + 8) * PSTRIDE + t0) = __floats2half2_rn(p2, p3);
        }

        // pre-issue the first two PV V-tile loads (depend only on KV buf, not sP)
        uint32_t bbase = kvb + pvB_off;
        uint32_t vb0[4], vb1[4];
        ldsm_x4t(vb0[0], vb0[1], vb0[2], vb0[3], bbase);
        ldsm_x4t(vb1[0], vb1[1], vb1[2], vb1[3], bbase + 16u);

        __syncthreads();   // B2: P visible

        // ---- PV: warp tile [32h x 64d] = P[32x32] @ V[32x64] ----
        {
            uint32_t ap[2][2][4];
            #pragma unroll
            for (int mi = 0; mi < 2; ++mi)
                #pragma unroll
                for (int k2 = 0; k2 < 2; ++k2) {
                    uint32_t aa = spb + (uint32_t)(((mi * 16 + (lt & 15)) * PSTRIDE + k2 * 16 + (lt >> 4) * 8) * 2);
                    ldsm_x4(ap[mi][k2][0], ap[mi][k2][1], ap[mi][k2][2], ap[mi][k2][3], aa);
                }
            // n2 = 0, 1 use preloaded V fragments
            #pragma unroll
            for (int mi = 0; mi < 2; ++mi) {
                mma16816(accO[mi][0][0], accO[mi][0][1], accO[mi][0][2], accO[mi][0][3],
                         ap[mi][0][0], ap[mi][0][1], ap[mi][0][2], ap[mi][0][3], vb0[0], vb0[1],
                         accO[mi][0][0], accO[mi][0][1], accO[mi][0][2], accO[mi][0][3]);
                mma16816(accO[mi][0][0], accO[mi][0][1], accO[mi][0][2], accO[mi][0][3],
                         ap[mi][1][0], ap[mi][1][1], ap[mi][1][2], ap[mi][1][3], vb0[2], vb0[3],
                         accO[mi][0][0], accO[mi][0][1], accO[mi][0][2], accO[mi][0][3]);
                mma16816(accO[mi][1][0], accO[mi][1][1], accO[mi][1][2], accO[mi][1][3],
                         ap[mi][0][0], ap[mi][0][1], ap[mi][0][2], ap[mi][0][3], vb1[0], vb1[1],
                         accO[mi][1][0], accO[mi][1][1], accO[mi][1][2], accO[mi][1][3]);
                mma16816(accO[mi][1][0], accO[mi][1][1], accO[mi][1][2], accO[mi][1][3],
                         ap[mi][1][0], ap[mi][1][1], ap[mi][1][2], ap[mi][1][3], vb1[2], vb1[3],
                         accO[mi][1][0], accO[mi][1][1], accO[mi][1][2], accO[mi][1][3]);
            }
            #pragma unroll
            for (int n2 = 2; n2 < 8; ++n2) {
                uint32_t b0, b1, b2, b3;
                ldsm_x4t(b0, b1, b2, b3, bbase + (uint32_t)(n2 * 16));
                #pragma unroll
                for (int mi = 0; mi < 2; ++mi)
                    mma16816(accO[mi][n2][0], accO[mi][n2][1], accO[mi][n2][2], accO[mi][n2][3],
                             ap[mi][0][0], ap[mi][0][1], ap[mi][0][2], ap[mi][0][3], b0, b1,
                             accO[mi][n2][0], accO[mi][n2][1], accO[mi][n2][2], accO[mi][n2][3]);
                #pragma unroll
                for (int mi = 0; mi < 2; ++mi)
                    mma16816(accO[mi][n2][0], accO[mi][n2][1], accO[mi][n2][2], accO[mi][n2][3],
                             ap[mi][1][0], ap[mi][1][1], ap[mi][1][2], ap[mi][1][3], b2, b3,
                             accO[mi][n2][0], accO[mi][n2][1], accO[mi][n2][2], accO[mi][n2][3]);
            }
        }

        // next tile's KV must be visible before anyone reads it next iteration
        if (hasNext) MB_WAIT(mbar + (((kt + 1) & 1) * 8), ((kt + 1) >> 1) & 1);
        __syncthreads();   // B3: PV done, sP/sPart reusable, gathered tile visible to all
    }

    // ---- epilogue ----
    {
        rs0 += __shfl_xor_sync(0xffffffffu, rs0, 1);
        rs0 += __shfl_xor_sync(0xffffffffu, rs0, 2);
        rs1 += __shfl_xor_sync(0xffffffffu, rs1, 1);
        rs1 += __shfl_xor_sync(0xffffffffu, rs1, 2);
        if ((lt & 3) == 0) {
            sLp[ks * 32 + rowa]     = rs0;
            sLp[ks * 32 + rowa + 8] = rs1;
        }
    }
    __syncthreads();

    {
        float* ob = out + ((size_t)tok * HH + hblk * HB) * DV;
        #pragma unroll
        for (int mi = 0; mi < 2; ++mi) {
            int r0 = mi * 16 + (lt >> 2);
            int r1 = r0 + 8;
            float d0 = sLp[r0] + sLp[32 + r0] + sLp[64 + r0] + sLp[96 + r0]
                     + __expf(sink[hblk * HB + r0]);
            float d1 = sLp[r1] + sLp[32 + r1] + sLp[64 + r1] + sLp[96 + r1]
                     + __expf(sink[hblk * HB + r1]);
            float rc0 = 1.0f / d0;
            float rc1 = 1.0f / d1;
            #pragma unroll
            for (int n2 = 0; n2 < 8; ++n2) {
                int d = w * 64 + n2 * 8 + (lt & 3) * 2;
                *(float2*)(ob + (size_t)r0 * DV + d) =
                    make_float2(accO[mi][n2][0] * rc0, accO[mi][n2][1] * rc0);
                *(float2*)(ob + (size_t)r1 * DV + d) =
                    make_float2(accO[mi][n2][2] * rc1, accO[mi][n2][3] * rc1);
            }
        }
    }
}

extern "C" void kernel_launch(void* const* d_in, const int* in_sizes, int n_in,
                              void* d_out, int out_size)
{
    const float* q    = (const float*)d_in[0];
    const float* kv   = (const float*)d_in[1];
    const int*   topk = (const int*)d_in[2];
    const float* sink = (const float*)d_in[3];
    float*       out  = (float*)d_out;

    kv_to_half_kernel<<<(NKV * DD / 4) / 256, 256>>>(kv);

    cudaFuncSetAttribute(mla_v11_kernel,
                         cudaFuncAttributeMaxDynamicSharedMemorySize, SMEM_BYTES);

    dim3 grid(HH / HB, TT);   // (2, 512)
    dim3 block(256);
    mla_v11_kernel<<<grid, block, SMEM_BYTES>>>(q, topk, sink, out);
}

// round 16
// speedup vs baseline: 1.4199x; 1.0150x over previous
#include <cuda_runtime.h>
#include <cuda_fp16.h>
#include <math.h>
#include <stdint.h>

#define TT     512
#define HH     64
#define DD     576
#define DV     512
#define NKV    8192
#define TOPK   1024
#define TILE   32
#define NTILES 32
#define HB     32
#define KSTRIDE 584               // halves per KV/Q smem row (1168 B)
#define ROWB   (KSTRIDE * 2)      // 1168 bytes
#define CPROW  1152               // bytes copied per KV row
#define PSTRIDE 40
#define KVBUF  (TILE * KSTRIDE)
#define SCALE_F (1.0f / 24.0f)
#define LOG2E   1.4426950408889634f
#define TILE_TX (TILE * CPROW)

#define SP_OFFB    (2 * KVBUF * 2)
#define SPART_OFFB (SP_OFFB + HB * PSTRIDE * 2)
#define SLP_OFFB   (SPART_OFFB + 8 * 4 * 32 * 4 * 4)
#define SIDX_OFFB  (SLP_OFFB + 4 * 32 * 4)
#define SMB_OFFB   (SIDX_OFFB + 2 * 32 * 4)
#define SMEM_BYTES (SMB_OFFB + 64)

__device__ __align__(16) half g_kvh[(size_t)NKV * DD];

__global__ void __launch_bounds__(256)
kv_to_half_kernel(const float* __restrict__ kv)
{
    size_t i = (size_t)blockIdx.x * 256 + threadIdx.x;
    float4 v = ((const float4*)kv)[i];
    half2 a = __floats2half2_rn(v.x, v.y);
    half2 b = __floats2half2_rn(v.z, v.w);
    uint2 u; u.x = *(uint32_t*)&a; u.y = *(uint32_t*)&b;
    ((uint2*)g_kvh)[i] = u;
}

__device__ __forceinline__ void ldsm_x4(uint32_t& r0, uint32_t& r1, uint32_t& r2, uint32_t& r3, uint32_t a) {
    asm volatile("ldmatrix.sync.aligned.m8n8.x4.shared.b16 {%0,%1,%2,%3}, [%4];"
                 : "=r"(r0), "=r"(r1), "=r"(r2), "=r"(r3) : "r"(a));
}
__device__ __forceinline__ void ldsm_x4t(uint32_t& r0, uint32_t& r1, uint32_t& r2, uint32_t& r3, uint32_t a) {
    asm volatile("ldmatrix.sync.aligned.m8n8.x4.trans.shared.b16 {%0,%1,%2,%3}, [%4];"
                 : "=r"(r0), "=r"(r1), "=r"(r2), "=r"(r3) : "r"(a));
}
__device__ __forceinline__ void mma16816(float& d0, float& d1, float& d2, float& d3,
                                         uint32_t a0, uint32_t a1, uint32_t a2, uint32_t a3,
                                         uint32_t b0, uint32_t b1,
                                         float c0, float c1, float c2, float c3) {
    asm volatile("mma.sync.aligned.m16n8k16.row.col.f32.f16.f16.f32 "
                 "{%0,%1,%2,%3},{%4,%5,%6,%7},{%8,%9},{%10,%11,%12,%13};"
                 : "=f"(d0), "=f"(d1), "=f"(d2), "=f"(d3)
                 : "r"(a0), "r"(a1), "r"(a2), "r"(a3), "r"(b0), "r"(b1),
                   "f"(c0), "f"(c1), "f"(c2), "f"(c3));
}
#define MB_WAIT(mb, ph) do { \
    asm volatile("{\n .reg .pred P1;\n WL%=:\n" \
        " mbarrier.try_wait.parity.acquire.cta.shared::cta.b64 P1, [%0], %1, 0x989680;\n" \
        " @P1 bra.uni WD%=;\n bra.uni WL%=;\n WD%=:\n}" :: "r"(mb), "r"(ph) : "memory"); \
} while (0)

__global__ void __launch_bounds__(256, 2)
mla_v12_kernel(const float* __restrict__ q,     // [T,H,D]
               const int*   __restrict__ topk,  // [T,TOPK]
               const float* __restrict__ sink,  // [H]
               float*       __restrict__ out)   // [T,H,DV]
{
    extern __shared__ char smem_raw[];
    half*  sKVh  = (half*)smem_raw;                       // [2][KVBUF]
    half*  sP    = (half*)(smem_raw + SP_OFFB);           // [32][40]
    float* sPart = (float*)(smem_raw + SPART_OFFB);       // [8 dst][4 src][32][4]
    float* sLp   = (float*)(smem_raw + SLP_OFFB);         // [4][32]
    int*   sIdx  = (int*)(smem_raw + SIDX_OFFB);          // [2][32]

    const int hblk = blockIdx.x;
    const int tok  = blockIdx.y;
    const int tid  = threadIdx.x;
    const int lt   = tid & 31;
    const int w    = tid >> 5;
    const int wrb  = w >> 2;           // head rowblock: 16 heads
    const int ks   = w & 3;            // k-split quarter; token n-tile; PV d-quarter

    const uint32_t skv0 = (uint32_t)__cvta_generic_to_shared(sKVh);
    const uint32_t spb  = (uint32_t)__cvta_generic_to_shared(sP);
    const uint32_t mbar = skv0 + SMB_OFFB;

    if (tid < 2) {
        asm volatile("mbarrier.init.shared.b64 [%0], 1;" :: "r"(mbar + tid * 8) : "memory");
    }

    // ---- stage Q (pre-scaled by 1/sqrt(D) * log2(e)) into sKV buf0 ----
    {
        const float qsc = SCALE_F * LOG2E;
        int h = tid >> 3, j = tid & 7;
        const float4* qs = (const float4*)(q + ((size_t)tok * HH + hblk * HB + h) * DD) + j;
        half* qd = sKVh + h * KSTRIDE;
        #pragma unroll
        for (int i = 0; i < 18; ++i) {
            float4 v = qs[i * 8];
            half2 h0 = __floats2half2_rn(v.x * qsc, v.y * qsc);
            half2 h1 = __floats2half2_rn(v.z * qsc, v.w * qsc);
            uint2 u; u.x = *(uint32_t*)&h0; u.y = *(uint32_t*)&h1;
            *(uint2*)(qd + j * 4 + i * 32) = u;
        }
    }
    __syncthreads();

    // Q A-fragments for this warp's 144-dim slice: 9 k-steps
    uint32_t qf[36];
    {
        uint32_t qa = skv0 + (uint32_t)(((wrb * 16 + (lt & 15)) * KSTRIDE + ks * 144 + (lt >> 4) * 8) * 2);
        #pragma unroll
        for (int s = 0; s < 9; ++s) {
            ldsm_x4(qf[4*s], qf[4*s+1], qf[4*s+2], qf[4*s+3], qa);
            qa += 32;
        }
    }
    __syncthreads();   // Q frags read before gather overwrites buf0

    const int* tkp = topk + (size_t)tok * TOPK;

    // ---- bulk gather: warp 0, one row per lane ----
    auto gather = [&](int tile) {
        int buf = tile & 1;
        int raw = tkp[tile * TILE + lt];
        sIdx[buf * 32 + lt] = raw;
        int r2 = raw < 0 ? 0 : raw;
        if (lt == 0) {
            asm volatile("mbarrier.arrive.expect_tx.shared.b64 _, [%0], %1;"
                         :: "r"(mbar + buf * 8), "r"((uint32_t)TILE_TX) : "memory");
        }
        __syncwarp();
        uint32_t dst = skv0 + (uint32_t)(buf * (KVBUF * 2) + lt * ROWB);
        const half* src = g_kvh + (size_t)r2 * DD;
        asm volatile("cp.async.bulk.shared::cta.global.mbarrier::complete_tx::bytes [%0], [%1], %2, [%3];"
                     :: "r"(dst), "l"(src), "r"((uint32_t)CPROW), "r"(mbar + buf * 8) : "memory");
    };

    // prologue: gather tile 0, wait, sync
    if (w == 0) gather(0);
    if (w == 0) MB_WAIT(mbar, 0);
    __syncthreads();

    // PV accumulator: [16 own-group heads x 128 dims] per warp
    float accO[16][4];
    #pragma unroll
    for (int n = 0; n < 16; ++n)
        accO[n][0] = accO[n][1] = accO[n][2] = accO[n][3] = 0.0f;

    float rs0 = 0.0f, rs1 = 0.0f;

    const uint32_t qkB_off = (uint32_t)(((lt & 15) * KSTRIDE + ks * 144 + (lt >> 4) * 8) * 2);
    const uint32_t pvB_off = (uint32_t)((lt * KSTRIDE + ks * 128) * 2);   // d-quarter base
    const int rowa = wrb * 16 + (lt >> 2);

    for (int kt = 0; kt < NTILES; ++kt) {
        const int cur = kt & 1;
        const uint32_t kvb = skv0 + (uint32_t)(cur * (KVBUF * 2));
        const bool hasNext = (kt + 1 < NTILES);

        // ---- issue next-tile bulk gather (warp 0; hides under whole tile body) ----
        if (hasNext && w == 0) gather(kt + 1);

        // ---- QK: warp tile [16h x 32t] over 144 dims (9 k-steps), A in registers ----
        float c[4][4];
        #pragma unroll
        for (int j = 0; j < 4; ++j) c[j][0] = c[j][1] = c[j][2] = c[j][3] = 0.0f;
        {
            uint32_t ka0 = kvb + qkB_off;
            uint32_t ka1 = ka0 + (uint32_t)(16 * KSTRIDE * 2);
            #pragma unroll
            for (int s = 0; s < 9; ++s) {
                uint32_t b0, b1, b2, b3;
                ldsm_x4(b0, b1, b2, b3, ka0); ka0 += 32;
                mma16816(c[0][0], c[0][1], c[0][2], c[0][3],
                         qf[4*s], qf[4*s+1], qf[4*s+2], qf[4*s+3], b0, b2,
                         c[0][0], c[0][1], c[0][2], c[0][3]);
                mma16816(c[1][0], c[1][1], c[1][2], c[1][3],
                         qf[4*s], qf[4*s+1], qf[4*s+2], qf[4*s+3], b1, b3,
                         c[1][0], c[1][1], c[1][2], c[1][3]);
                uint32_t e0, e1, e2, e3;
                ldsm_x4(e0, e1, e2, e3, ka1); ka1 += 32;
                mma16816(c[2][0], c[2][1], c[2][2], c[2][3],
                         qf[4*s], qf[4*s+1], qf[4*s+2], qf[4*s+3], e0, e2,
                         c[2][0], c[2][1], c[2][2], c[2][3]);
                mma16816(c[3][0], c[3][1], c[3][2], c[3][3],
                         qf[4*s], qf[4*s+1], qf[4*s+2], qf[4*s+3], e1, e3,
                         c[3][0], c[3][1], c[3][2], c[3][3]);
            }
        }

        // export the 3 token n-tiles owned by partner warps (SAME wrb group)
        #pragma unroll
        for (int j = 0; j < 4; ++j) {
            if (j != ks) {
                float* pb = sPart + (((wrb * 4 + j) * 4 + ks) * 32 + lt) * 4;
                *(float4*)pb = make_float4(c[j][0], c[j][1], c[j][2], c[j][3]);
            }
        }
        // B1 (named, per wrb group): exchange is wrb-local
        asm volatile("bar.sync %0, 128;" :: "r"(1 + wrb) : "memory");

        // ---- softmax (fixed base 0, log2 domain) on own n-tile ----
        {
            float s0 = c[ks][0], s1 = c[ks][1], s2 = c[ks][2], s3 = c[ks][3];
            #pragma unroll
            for (int src = 0; src < 4; ++src) {
                if (src != ks) {
                    float4 pp = *(const float4*)(sPart + ((w * 4 + src) * 32 + lt) * 4);
                    s0 += pp.x; s1 += pp.y; s2 += pp.z; s3 += pp.w;
                }
            }
            int t0 = ks * 8 + (lt & 3) * 2;
            int i0 = sIdx[cur * 32 + t0];
            int i1 = sIdx[cur * 32 + t0 + 1];
            float p0 = (i0 < 0) ? 0.f : exp2f(s0);
            float p1 = (i1 < 0) ? 0.f : exp2f(s1);
            float p2 = (i0 < 0) ? 0.f : exp2f(s2);
            float p3 = (i1 < 0) ? 0.f : exp2f(s3);
            rs0 += p0 + p1;
            rs1 += p2 + p3;
            *(half2*)(sP + rowa * PSTRIDE + t0)       = __floats2half2_rn(p0, p1);
            *(half2*)(sP + (rowa + 8) * PSTRIDE + t0) = __floats2half2_rn(p2, p3);
        }

        // pre-issue the first two PV V-tile loads (depend only on KV buf, not sP)
        uint32_t bbase = kvb + pvB_off;
        uint32_t vb0[4], vb1[4];
        ldsm_x4t(vb0[0], vb0[1], vb0[2], vb0[3], bbase);
        ldsm_x4t(vb1[0], vb1[1], vb1[2], vb1[3], bbase + 16u);

        // B2 (named, per wrb group): PV reads only own-group P rows
        asm volatile("bar.sync %0, 128;" :: "r"(1 + wrb) : "memory");

        // ---- PV: warp tile [16h x 128d] = P[16x32](own group) @ V[32x128] ----
        {
            uint32_t ap[2][4];
            #pragma unroll
            for (int k2 = 0; k2 < 2; ++k2) {
                uint32_t aa = spb + (uint32_t)(((wrb * 16 + (lt & 15)) * PSTRIDE + k2 * 16 + (lt >> 4) * 8) * 2);
                ldsm_x4(ap[k2][0], ap[k2][1], ap[k2][2], ap[k2][3], aa);
            }
            // n2 = 0, 1 use preloaded V fragments
            mma16816(accO[0][0], accO[0][1], accO[0][2], accO[0][3],
                     ap[0][0], ap[0][1], ap[0][2], ap[0][3], vb0[0], vb0[1],
                     accO[0][0], accO[0][1], accO[0][2], accO[0][3]);
            mma16816(accO[0][0], accO[0][1], accO[0][2], accO[0][3],
                     ap[1][0], ap[1][1], ap[1][2], ap[1][3], vb0[2], vb0[3],
                     accO[0][0], accO[0][1], accO[0][2], accO[0][3]);
            mma16816(accO[1][0], accO[1][1], accO[1][2], accO[1][3],
                     ap[0][0], ap[0][1], ap[0][2], ap[0][3], vb1[0], vb1[1],
                     accO[1][0], accO[1][1], accO[1][2], accO[1][3]);
            mma16816(accO[1][0], accO[1][1], accO[1][2], accO[1][3],
                     ap[1][0], ap[1][1], ap[1][2], ap[1][3], vb1[2], vb1[3],
                     accO[1][0], accO[1][1], accO[1][2], accO[1][3]);
            #pragma unroll
            for (int n2 = 2; n2 < 16; ++n2) {
                uint32_t b0, b1, b2, b3;
                ldsm_x4t(b0, b1, b2, b3, bbase + (uint32_t)(n2 * 16));
                mma16816(accO[n2][0], accO[n2][1], accO[n2][2], accO[n2][3],
                         ap[0][0], ap[0][1], ap[0][2], ap[0][3], b0, b1,
                         accO[n2][0], accO[n2][1], accO[n2][2], accO[n2][3]);
                mma16816(accO[n2][0], accO[n2][1], accO[n2][2], accO[n2][3],
                         ap[1][0], ap[1][1], ap[1][2], ap[1][3], b2, b3,
                         accO[n2][0], accO[n2][1], accO[n2][2], accO[n2][3]);
            }
        }

        // next tile's KV must be visible before anyone reads it next iteration
        if (hasNext && w == 0) MB_WAIT(mbar + (((kt + 1) & 1) * 8), ((kt + 1) >> 1) & 1);
        __syncthreads();   // B3 (block): PV done everywhere; buffers rotate; TMA data visible
    }

    // ---- epilogue ----
    {
        rs0 += __shfl_xor_sync(0xffffffffu, rs0, 1);
        rs0 += __shfl_xor_sync(0xffffffffu, rs0, 2);
        rs1 += __shfl_xor_sync(0xffffffffu, rs1, 1);
        rs1 += __shfl_xor_sync(0xffffffffu, rs1, 2);
        if ((lt & 3) == 0) {
            sLp[ks * 32 + rowa]     = rs0;
            sLp[ks * 32 + rowa + 8] = rs1;
        }
    }
    __syncthreads();

    {
        float* ob = out + ((size_t)tok * HH + hblk * HB) * DV;
        int r0 = rowa;
        int r1 = rowa + 8;
        float d0 = sLp[r0] + sLp[32 + r0] + sLp[64 + r0] + sLp[96 + r0]
                 + __expf(sink[hblk * HB + r0]);
        float d1 = sLp[r1] + sLp[32 + r1] + sLp[64 + r1] + sLp[96 + r1]
                 + __expf(sink[hblk * HB + r1]);
        float rc0 = 1.0f / d0;
        float rc1 = 1.0f / d1;
        #pragma unroll
        for (int n2 = 0; n2 < 16; ++n2) {
            int d = ks * 128 + n2 * 8 + (lt & 3) * 2;
            *(float2*)(ob + (size_t)r0 * DV + d) =
                make_float2(accO[n2][0] * rc0, accO[n2][1] * rc0);
            *(float2*)(ob + (size_t)r1 * DV + d) =
                make_float2(accO[n2][2] * rc1, accO[n2][3] * rc1);
        }
    }
}

extern "C" void kernel_launch(void* const* d_in, const int* in_sizes, int n_in,
                              void* d_out, int out_size)
{
    const float* q    = (const float*)d_in[0];
    const float* kv   = (const float*)d_in[1];
    const int*   topk = (const int*)d_in[2];
    const float* sink = (const float*)d_in[3];
    float*       out  = (float*)d_out;

    kv_to_half_kernel<<<(NKV * DD / 4) / 256, 256>>>(kv);

    cudaFuncSetAttribute(mla_v12_kernel,
                         cudaFuncAttributeMaxDynamicSharedMemorySize, SMEM_BYTES);

    dim3 grid(HH / HB, TT);   // (2, 512)
    dim3 block(256);
    mla_v12_kernel<<<grid, block, SMEM_BYTES>>>(q, topk, sink, out);
}